// round 7
// baseline (speedup 1.0000x reference)
#include <cuda_runtime.h>
#include <math.h>

typedef unsigned long long ull;

#define B_    16
#define H_    32
#define W_    32
#define CI    8
#define AI    32
#define KS    5
#define CO    16
#define AO    16
#define COAO  256
#define PADW  36
#define TAPF  (AI * COAO)   /* 8192 floats per conv tap */

// votes scratch: [pix(B*H*W)][ci][co*ao]  = 33,554,432 floats = 128 MiB
__device__ float g_votes[(size_t)B_ * H_ * W_ * CI * COAO];

__device__ __forceinline__ void cp16(void* dst, const void* src) {
    unsigned d = (unsigned)__cvta_generic_to_shared(dst);
    asm volatile("cp.async.cg.shared.global [%0], [%1], 16;" :: "r"(d), "l"(src));
}

#define FMA2(acc, a, b) \
    asm("fma.rn.f32x2 %0, %1, %2, %0;" : "+l"(acc) : "l"(a), "l"(b))

// ---------------------------------------------------------------------------
// Conv kernel: one CTA per (b, ci, h). Computes votes for 32 pixels x 256 out
// channels. Input halo in SMEM (values duplicated -> f32x2-ready), weights
// streamed per tap via cp.async double buffer.
// ---------------------------------------------------------------------------
__global__ void __launch_bounds__(256, 2)
conv_kernel(const float* __restrict__ x, const float* __restrict__ Wg) {
    extern __shared__ float smem[];
    float* s_in = smem;                    // 5 * 32 * (2*36) = 11520 floats (dup pairs)
    float* s_w  = smem + KS * AI * 2 * PADW;  // 2 * 8192 floats

    const int tid = threadIdx.x;
    const int h  = blockIdx.x;
    const int ci = blockIdx.y;
    const int b  = blockIdx.z;

    // Prefetch tap 0 weights (overlaps with input halo load)
    {
        #pragma unroll
        for (int i = 0; i < 8; ++i) {
            int off = tid * 4 + i * 1024;
            cp16(s_w + off, Wg + off);
        }
        asm volatile("cp.async.commit_group;");
    }

    // Load input halo rows h-2..h+2, zero-padded, each value duplicated so
    // ld.shared.b64 yields a packed {v, v} f32x2 operand.
    for (int i = tid; i < KS * PADW * AI; i += 256) {
        int a   = i & 31;
        int t2  = i >> 5;
        int col = t2 % PADW;
        int r   = t2 / PADW;
        int hh  = h + r - 2;
        int ww  = col - 2;
        float v = 0.f;
        if ((unsigned)hh < 32u && (unsigned)ww < 32u)
            v = x[(((size_t)(b * H_ + hh) * W_ + ww) * (CI * AI)) + ci * AI + a];
        float* p = s_in + ((r * AI + a) * (2 * PADW)) + col * 2;
        p[0] = v;
        p[1] = v;
    }

    const int cg = tid & 31;   // channel group: channels cg*8 .. cg*8+7
    const int pg = tid >> 5;   // pixel group:   pixels pg*4 .. pg*4+3

    ull acc[4][4];
    #pragma unroll
    for (int p = 0; p < 4; ++p)
        #pragma unroll
        for (int c = 0; c < 4; ++c) acc[p][c] = 0ull;

    int t = 0;
    #pragma unroll 1
    for (int dy = 0; dy < KS; ++dy) {
        #pragma unroll 1
        for (int dx = 0; dx < KS; ++dx, ++t) {
            // Prefetch next tap into the other buffer
            if (t + 1 < 25) {
                const float* src = Wg + (size_t)(t + 1) * TAPF;
                float* dst = s_w + ((t + 1) & 1) * TAPF;
                #pragma unroll
                for (int i = 0; i < 8; ++i) {
                    int off = tid * 4 + i * 1024;
                    cp16(dst + off, src + off);
                }
                asm volatile("cp.async.commit_group;");
                asm volatile("cp.async.wait_group 1;");
            } else {
                asm volatile("cp.async.wait_group 0;");
            }
            __syncthreads();

            const float* sw  = s_w + (t & 1) * TAPF + cg * 8;
            const float* sip = s_in + dy * (AI * 2 * PADW) + (pg * 4 + dx) * 2;

            #pragma unroll 8
            for (int a = 0; a < AI; ++a) {
                ulonglong2 wA = *(const ulonglong2*)(sw + a * COAO);
                ulonglong2 wB = *(const ulonglong2*)(sw + a * COAO + 4);
                const float* ip = sip + a * (2 * PADW);
                #pragma unroll
                for (int p = 0; p < 4; ++p) {
                    ull iv = *(const ull*)(ip + 2 * p);   // {v, v} pre-duplicated
                    FMA2(acc[p][0], iv, wA.x);
                    FMA2(acc[p][1], iv, wA.y);
                    FMA2(acc[p][2], iv, wB.x);
                    FMA2(acc[p][3], iv, wB.y);
                }
            }
            __syncthreads();   // protect s_w buffer before next prefetch overwrites it
        }
    }

    // Write votes: votes[pix][ci][coao]
    const int pixrow = (b * H_ + h) * W_;
    #pragma unroll
    for (int p = 0; p < 4; ++p) {
        int w = pg * 4 + p;
        float* o = g_votes + ((size_t)(pixrow + w)) * (CI * COAO) + ci * COAO + cg * 8;
        float4 f0, f1;
        asm("mov.b64 {%0,%1}, %2;" : "=f"(f0.x), "=f"(f0.y) : "l"(acc[p][0]));
        asm("mov.b64 {%0,%1}, %2;" : "=f"(f0.z), "=f"(f0.w) : "l"(acc[p][1]));
        asm("mov.b64 {%0,%1}, %2;" : "=f"(f1.x), "=f"(f1.y) : "l"(acc[p][2]));
        asm("mov.b64 {%0,%1}, %2;" : "=f"(f1.z), "=f"(f1.w) : "l"(acc[p][3]));
        *(float4*)o       = f0;
        *(float4*)(o + 4) = f1;
    }
}

// ---------------------------------------------------------------------------
// Routing kernel: one CTA per pixel. All 3 routing iterations fused in SMEM.
// Thread t <-> (co = t>>4, ao = t&15). Softmax over Co and squash over Ao via
// 16-lane shuffle reductions.
// ---------------------------------------------------------------------------
__global__ void __launch_bounds__(256)
routing_kernel(const float* __restrict__ bias, float* __restrict__ out) {
    __shared__ float v[CI * COAO];   // 2048 floats: votes slice for this pixel
    __shared__ float lg[CI * CO];    // logits
    __shared__ float rt[CI * CO];    // route (softmax)
    __shared__ float act[COAO];      // activation

    const int t   = threadIdx.x;
    const int pix = blockIdx.x;

    const float* vp = g_votes + (size_t)pix * (CI * COAO);
    for (int i = t; i < CI * COAO; i += 256) v[i] = vp[i];
    const float bv = bias[t];
    if (t < 128) lg[t] = 0.f;
    __syncthreads();

    const int co = t >> 4;
    float a_reg = 0.f;

    #pragma unroll 1
    for (int it = 0; it < 3; ++it) {
        // route = softmax(logits over Co). t<128: (ci = t>>4, co' = t&15);
        // co' == lane&15, so width-16 shuffles reduce exactly over Co.
        if (t < 128) {
            float lv = lg[t];
            float m = lv;
            #pragma unroll
            for (int o = 8; o; o >>= 1)
                m = fmaxf(m, __shfl_xor_sync(0xffffffffu, m, o, 16));
            float e = expf(lv - m);
            float s = e;
            #pragma unroll
            for (int o = 8; o; o >>= 1)
                s += __shfl_xor_sync(0xffffffffu, s, o, 16);
            rt[t] = e / s;
        }
        __syncthreads();

        // preact[co][ao] = bias + sum_ci route[ci][co] * votes[ci][co][ao]
        float p = bv;
        #pragma unroll
        for (int c = 0; c < CI; ++c)
            p += rt[c * CO + co] * v[c * COAO + t];

        // squash: norm over Ao (ao == lane&15 -> width-16 shuffle reduction)
        float ns = p * p;
        #pragma unroll
        for (int o = 8; o; o >>= 1)
            ns += __shfl_xor_sync(0xffffffffu, ns, o, 16);
        a_reg = p * (sqrtf(ns) / (1.0f + ns));
        act[t] = a_reg;
        __syncthreads();

        // logits[ci][co] += sum_ao votes[ci][co][ao] * act[co][ao]
        if (it < 2) {
            if (t < 128) {
                const int c2 = t & 15;   // co
                const int c1 = t >> 4;   // ci
                float s = 0.f;
                #pragma unroll
                for (int a = 0; a < AO; ++a)
                    s += v[c1 * COAO + c2 * AO + a] * act[c2 * AO + a];
                lg[t] += s;
            }
            __syncthreads();
        }
    }

    out[(size_t)pix * COAO + t] = a_reg;
}

// ---------------------------------------------------------------------------
extern "C" void kernel_launch(void* const* d_in, const int* in_sizes, int n_in,
                              void* d_out, int out_size) {
    const float* x  = (const float*)d_in[0];   // [16,32,32,8,32]
    const float* Wg = (const float*)d_in[1];   // [5,5,32,256]
    const float* bb = (const float*)d_in[2];   // [1,1,16,16]
    float* out = (float*)d_out;                // [16,32,32,16,16]

    const int smem_bytes = (KS * AI * 2 * PADW + 2 * TAPF) * (int)sizeof(float); // 111,616 B
    cudaFuncSetAttribute(conv_kernel,
                         cudaFuncAttributeMaxDynamicSharedMemorySize, smem_bytes);

    dim3 grid(H_, CI, B_);
    conv_kernel<<<grid, 256, smem_bytes>>>(x, Wg);
    routing_kernel<<<B_ * H_ * W_, 256>>>(bb, out);
}

// round 11
// speedup vs baseline: 4.2910x; 4.2910x over previous
#include <cuda_runtime.h>
#include <math.h>
#include <stdint.h>

#define B_   16
#define H_   32
#define Wd_  32
#define CI   8
#define AI   32
#define CO   16
#define AO   16
#define COAO 256

// votes scratch [pix][ci][co*ao] = 33.5M floats = 128 MiB
__device__ float g_votes[(size_t)B_ * H_ * Wd_ * CI * COAO];
// fragment-order tf32 weights: [tap 25][nt 32][lane 32][slot 8]
//   value(tap,nt,l,j) = tf32( W[(tap*32 + (l&3) + 4*j)*256 + nt*8 + (l>>2)] )
__device__ float g_Bf[25 * 32 * 32 * 8];

// ---- SMEM layout (bytes) --------------------------------------------------
// patch: 8 halo rows x 36 cols x 36 floats (32 atoms + 4 pad) = 41472 B
//   addr(row36, a) = (row36*36 + a)*4 ; stride between consecutive w = 36 floats
//   -> A-fragment banks = (4*m + q) mod 32 : conflict-free
#define PATCH_BYTES 41472
// B buffers: 2 x [32 nt][32 lane][12 floats (8 used)] = 2 x 49152 B
#define BBUF_BYTES  49152
#define SMEM_BYTES  (PATCH_BYTES + 2 * BBUF_BYTES)   // 139776

__device__ __forceinline__ float tf32r(float f) {
    uint32_t u; asm("cvt.rna.tf32.f32 %0, %1;" : "=r"(u) : "f"(f));
    return __uint_as_float(u);
}
__device__ __forceinline__ void cp16(void* dst, const void* src) {
    unsigned d = (unsigned)__cvta_generic_to_shared(dst);
    asm volatile("cp.async.cg.shared.global [%0], [%1], 16;" :: "r"(d), "l"(src));
}

#define MMA(d, A, b0, b1) \
    asm volatile( \
        "mma.sync.aligned.m16n8k8.row.col.f32.tf32.tf32.f32 " \
        "{%0,%1,%2,%3}, {%4,%5,%6,%7}, {%8,%9}, {%0,%1,%2,%3};" \
        : "+f"((d)[0]), "+f"((d)[1]), "+f"((d)[2]), "+f"((d)[3]) \
        : "r"((A)[0]), "r"((A)[1]), "r"((A)[2]), "r"((A)[3]), \
          "r"(b0), "r"(b1))

// ---------------------------------------------------------------------------
// Precompute fragment-order tf32 weights.
// ---------------------------------------------------------------------------
__global__ void __launch_bounds__(256)
bfrag_kernel(const float* __restrict__ W) {
    const int tap = blockIdx.x;          // 0..24
    const int nt  = blockIdx.y;          // 0..31
    const int t   = threadIdx.x;
    const int j   = t & 7;               // slot
    const int l   = t >> 3;              // lane
    const int q   = l & 3;
    const int k   = q + 4 * j;           // 0..31 within tap
    const int n   = nt * 8 + (l >> 2);
    g_Bf[((tap * 32 + nt) * 32 + l) * 8 + j] =
        tf32r(W[(tap * 32 + k) * COAO + n]);
}

// ---------------------------------------------------------------------------
// Conv kernel: tf32 mma.sync GEMM. CTA = (hq, ci, b): M = 4h x 32w = 128,
// N = 256 (full). 8 warps = 2(M) x 4(N); warp tile 64 x 64.
// ---------------------------------------------------------------------------
__global__ void __launch_bounds__(256, 1)
conv_kernel(const float* __restrict__ x) {
    extern __shared__ float smem[];
    float* patch = smem;
    char*  bbuf  = (char*)smem + PATCH_BYTES;

    const int tid = threadIdx.x;
    const int wid = tid >> 5, lid = tid & 31;
    const int hq = blockIdx.x, ci = blockIdx.y, b = blockIdx.z;
    const int h0 = hq * 4;

    // ---- prefetch B tap 0 (overlaps patch load) ----
    {
        const float* src = g_Bf;                 // tap 0
        #pragma unroll
        for (int ii = 0; ii < 8; ++ii) {
            int i    = tid + ii * 256;           // 0..2047 (16B chunks)
            int half = i & 1;
            int nl   = i >> 1;                   // nt*32 + lane, 0..1023
            cp16(bbuf + (nl * 12 + half * 4) * 4, src + nl * 8 + half * 4);
        }
        asm volatile("cp.async.commit_group;");
    }

    // ---- load halo patch: rows h0-2..h0+5, cols -2..33, 32 atoms, tf32 ----
    #pragma unroll
    for (int ii = 0; ii < 9; ++ii) {
        int i   = tid + ii * 256;                // 0..2303 float4s
        int a4  = i & 7;
        int r36 = i >> 3;                        // 0..287 = hi*36 + ww
        int ww  = r36 % 36;
        int hi  = r36 / 36;
        int hg  = h0 + hi - 2, wg = ww - 2;
        float4 v = make_float4(0.f, 0.f, 0.f, 0.f);
        if ((unsigned)hg < 32u && (unsigned)wg < 32u)
            v = *(const float4*)(x + ((((size_t)(b * 32 + hg) * 32 + wg) * CI
                                       + ci) * AI + a4 * 4));
        v.x = tf32r(v.x); v.y = tf32r(v.y); v.z = tf32r(v.z); v.w = tf32r(v.w);
        *(float4*)(patch + (size_t)r36 * 36 + a4 * 4) = v;
    }

    const int wm = wid >> 2, wn = wid & 3;       // warp M/N coords
    const int r = lid >> 2, q = lid & 3;

    // per-mt patch base (row36 of output pixel), constant across taps
    int rowbase[4]; int wcol[4];
    #pragma unroll
    for (int mt = 0; mt < 4; ++mt) {
        int m = wm * 64 + mt * 16 + r;           // m = hi2*32 + w
        rowbase[mt] = (m >> 5) * 36;
        wcol[mt]    = m & 31;
    }

    float acc[4][8][4];
    #pragma unroll
    for (int mt = 0; mt < 4; ++mt)
        #pragma unroll
        for (int nt = 0; nt < 8; ++nt)
            #pragma unroll
            for (int k = 0; k < 4; ++k) acc[mt][nt][k] = 0.f;

    #pragma unroll 1
    for (int t = 0; t < 25; ++t) {
        asm volatile("cp.async.wait_group 0;");
        __syncthreads();   // tap t visible; all warps done with buffer (t+1)&1

        if (t + 1 < 25) {  // prefetch next tap into the other buffer
            const float* src = g_Bf + (size_t)(t + 1) * (32 * 32 * 8);
            char* dst = bbuf + ((t + 1) & 1) * BBUF_BYTES;
            #pragma unroll
            for (int ii = 0; ii < 8; ++ii) {
                int i    = tid + ii * 256;
                int half = i & 1;
                int nl   = i >> 1;
                cp16(dst + (nl * 12 + half * 4) * 4, src + nl * 8 + half * 4);
            }
            asm volatile("cp.async.commit_group;");
        }

        const int dy = t / 5, dx = t % 5;
        const float* apt[4];
        #pragma unroll
        for (int mt = 0; mt < 4; ++mt)
            apt[mt] = patch + (size_t)(rowbase[mt] + dy * 36 + wcol[mt] + dx) * 36 + q;

        const char* bb = bbuf + (t & 1) * BBUF_BYTES;

        #pragma unroll
        for (int ksp = 0; ksp < 2; ++ksp) {
            uint4 bf[8];
            #pragma unroll
            for (int nt = 0; nt < 8; ++nt)
                bf[nt] = *(const uint4*)(bb +
                    (((wn * 8 + nt) * 32 + lid) * 12 + ksp * 4) * 4);

            #pragma unroll
            for (int ks2 = 0; ks2 < 2; ++ks2) {
                const int ko = (ksp * 2 + ks2) * 8;
                uint32_t A[4][4];
                #pragma unroll
                for (int mt = 0; mt < 4; ++mt) {
                    const float* p = apt[mt] + ko;
                    A[mt][0] = __float_as_uint(p[0]);
                    A[mt][1] = __float_as_uint(p[288]);   // row +8 (8*36)
                    A[mt][2] = __float_as_uint(p[4]);
                    A[mt][3] = __float_as_uint(p[292]);
                }
                #pragma unroll
                for (int mt = 0; mt < 4; ++mt)
                    #pragma unroll
                    for (int nt = 0; nt < 8; ++nt) {
                        uint32_t b0 = ks2 ? bf[nt].z : bf[nt].x;
                        uint32_t b1 = ks2 ? bf[nt].w : bf[nt].y;
                        MMA(acc[mt][nt], A[mt], b0, b1);
                    }
            }
        }
    }

    // ---- epilogue: store votes directly from accumulators ----
    #pragma unroll
    for (int mt = 0; mt < 4; ++mt) {
        int m   = wm * 64 + mt * 16 + r;
        int hi2 = m >> 5, w = m & 31;
        size_t base0 = (((size_t)(b * 32 + h0 + hi2)) * 32 + w) * 2048
                     + ci * 256 + wn * 64 + 2 * q;
        size_t base1 = base0 + 8 * 2048;         // row r+8 (same hi2)
        #pragma unroll
        for (int nt = 0; nt < 8; ++nt) {
            *(float2*)(g_votes + base0 + nt * 8) =
                make_float2(acc[mt][nt][0], acc[mt][nt][1]);
            *(float2*)(g_votes + base1 + nt * 8) =
                make_float2(acc[mt][nt][2], acc[mt][nt][3]);
        }
    }
}

// ---------------------------------------------------------------------------
// Routing kernel: votes in registers, logits/route in SMEM.
// Thread t = co*16 + ao; 16-lane shuffle reductions.
// ---------------------------------------------------------------------------
__global__ void __launch_bounds__(256)
routing_kernel(const float* __restrict__ bias, float* __restrict__ out) {
    __shared__ float lg[128];   // logits [ci][co]
    __shared__ float rt[128];   // route  [ci][co]

    const int t   = threadIdx.x;
    const int pix = blockIdx.x;
    const int co  = t >> 4, ao = t & 15;

    float v[8];
    const float* vp = g_votes + (size_t)pix * 2048 + t;
    #pragma unroll
    for (int c = 0; c < 8; ++c) v[c] = vp[c * 256];
    const float bv = __ldg(bias + t);
    if (t < 128) lg[t] = 0.f;
    __syncthreads();

    float a = 0.f;
    #pragma unroll 1
    for (int it = 0; it < 3; ++it) {
        if (t < 128) {   // (ci = t>>4, co' = t&15): softmax over co'
            float lv = lg[t];
            float m = lv;
            #pragma unroll
            for (int o = 8; o; o >>= 1)
                m = fmaxf(m, __shfl_xor_sync(0xffffffffu, m, o, 16));
            float e = expf(lv - m);
            float ssum = e;
            #pragma unroll
            for (int o = 8; o; o >>= 1)
                ssum += __shfl_xor_sync(0xffffffffu, ssum, o, 16);
            rt[t] = e / ssum;
        }
        __syncthreads();

        float p = bv;
        #pragma unroll
        for (int c = 0; c < 8; ++c) p += rt[c * 16 + co] * v[c];

        float ns = p * p;
        #pragma unroll
        for (int o = 8; o; o >>= 1)
            ns += __shfl_xor_sync(0xffffffffu, ns, o, 16);
        a = p * (sqrtf(ns) / (1.0f + ns));

        if (it < 2) {
            float sc[8];
            #pragma unroll
            for (int c = 0; c < 8; ++c) sc[c] = v[c] * a;
            #pragma unroll
            for (int o = 8; o; o >>= 1)
                #pragma unroll
                for (int c = 0; c < 8; ++c)
                    sc[c] += __shfl_xor_sync(0xffffffffu, sc[c], o, 16);
            if (ao == 0) {
                #pragma unroll
                for (int c = 0; c < 8; ++c) lg[c * 16 + co] += sc[c];
            }
            __syncthreads();
        }
    }
    out[(size_t)pix * 256 + t] = a;
}

// ---------------------------------------------------------------------------
extern "C" void kernel_launch(void* const* d_in, const int* in_sizes, int n_in,
                              void* d_out, int out_size) {
    const float* x  = (const float*)d_in[0];   // [16,32,32,8,32]
    const float* Wg = (const float*)d_in[1];   // [5,5,32,256]
    const float* bb = (const float*)d_in[2];   // [1,1,16,16]
    float* out = (float*)d_out;                // [16,32,32,16,16]

    cudaFuncSetAttribute(conv_kernel,
                         cudaFuncAttributeMaxDynamicSharedMemorySize, SMEM_BYTES);

    bfrag_kernel<<<dim3(25, 32), 256>>>(Wg);
    conv_kernel<<<dim3(8, CI, B_), 256, SMEM_BYTES>>>(x);
    routing_kernel<<<B_ * H_ * Wd_, 256>>>(bb, out);
}

// round 12
// speedup vs baseline: 4.2937x; 1.0006x over previous
#include <cuda_runtime.h>
#include <math.h>
#include <stdint.h>

#define B_   16
#define H_   32
#define Wd_  32
#define CI   8
#define AI   32
#define CO   16
#define AO   16
#define COAO 256

// votes scratch [pix][ci][co*ao] = 33.5M floats = 128 MiB
__device__ float g_votes[(size_t)B_ * H_ * Wd_ * CI * COAO];
// fragment-order tf32 weights: [tap 25][nt 32][lane 32][slot 8]
//   value(tap,nt,l,j) = tf32( W[(tap*32 + (l&3) + 4*j)*256 + nt*8 + (l>>2)] )
__device__ float g_Bf[25 * 32 * 32 * 8];

// ---- SMEM layout (bytes) --------------------------------------------------
// patch: 8 halo rows x 36 cols x 36 floats (32 atoms + 4 pad) = 41472 B
//   addr(row36, a) = (row36*36 + a)*4 ; stride between consecutive w = 36 floats
//   -> A-fragment banks = (4*m + q) mod 32 : conflict-free
#define PATCH_BYTES 41472
// B buffers: 2 x [32 nt][32 lane][12 floats (8 used)] = 2 x 49152 B
#define BBUF_BYTES  49152
#define SMEM_BYTES  (PATCH_BYTES + 2 * BBUF_BYTES)   // 139776

__device__ __forceinline__ float tf32r(float f) {
    uint32_t u; asm("cvt.rna.tf32.f32 %0, %1;" : "=r"(u) : "f"(f));
    return __uint_as_float(u);
}
__device__ __forceinline__ void cp16(void* dst, const void* src) {
    unsigned d = (unsigned)__cvta_generic_to_shared(dst);
    asm volatile("cp.async.cg.shared.global [%0], [%1], 16;" :: "r"(d), "l"(src));
}

#define MMA(d, A, b0, b1) \
    asm volatile( \
        "mma.sync.aligned.m16n8k8.row.col.f32.tf32.tf32.f32 " \
        "{%0,%1,%2,%3}, {%4,%5,%6,%7}, {%8,%9}, {%0,%1,%2,%3};" \
        : "+f"((d)[0]), "+f"((d)[1]), "+f"((d)[2]), "+f"((d)[3]) \
        : "r"((A)[0]), "r"((A)[1]), "r"((A)[2]), "r"((A)[3]), \
          "r"(b0), "r"(b1))

// ---------------------------------------------------------------------------
// Precompute fragment-order tf32 weights.
// ---------------------------------------------------------------------------
__global__ void __launch_bounds__(256)
bfrag_kernel(const float* __restrict__ W) {
    const int tap = blockIdx.x;          // 0..24
    const int nt  = blockIdx.y;          // 0..31
    const int t   = threadIdx.x;
    const int j   = t & 7;               // slot
    const int l   = t >> 3;              // lane
    const int q   = l & 3;
    const int k   = q + 4 * j;           // 0..31 within tap
    const int n   = nt * 8 + (l >> 2);
    g_Bf[((tap * 32 + nt) * 32 + l) * 8 + j] =
        tf32r(W[(tap * 32 + k) * COAO + n]);
}

// ---------------------------------------------------------------------------
// Conv kernel: tf32 mma.sync GEMM. CTA = (hq, ci, b): M = 4h x 32w = 128,
// N = 256 (full). 8 warps = 2(M) x 4(N); warp tile 64 x 64.
// ---------------------------------------------------------------------------
__global__ void __launch_bounds__(256, 1)
conv_kernel(const float* __restrict__ x) {
    extern __shared__ float smem[];
    float* patch = smem;
    char*  bbuf  = (char*)smem + PATCH_BYTES;

    const int tid = threadIdx.x;
    const int wid = tid >> 5, lid = tid & 31;
    const int hq = blockIdx.x, ci = blockIdx.y, b = blockIdx.z;
    const int h0 = hq * 4;

    // ---- prefetch B tap 0 (overlaps patch load) ----
    {
        const float* src = g_Bf;                 // tap 0
        #pragma unroll
        for (int ii = 0; ii < 8; ++ii) {
            int i    = tid + ii * 256;           // 0..2047 (16B chunks)
            int half = i & 1;
            int nl   = i >> 1;                   // nt*32 + lane, 0..1023
            cp16(bbuf + (nl * 12 + half * 4) * 4, src + nl * 8 + half * 4);
        }
        asm volatile("cp.async.commit_group;");
    }

    // ---- load halo patch: rows h0-2..h0+5, cols -2..33, 32 atoms, tf32 ----
    #pragma unroll
    for (int ii = 0; ii < 9; ++ii) {
        int i   = tid + ii * 256;                // 0..2303 float4s
        int a4  = i & 7;
        int r36 = i >> 3;                        // 0..287 = hi*36 + ww
        int ww  = r36 % 36;
        int hi  = r36 / 36;
        int hg  = h0 + hi - 2, wg = ww - 2;
        float4 v = make_float4(0.f, 0.f, 0.f, 0.f);
        if ((unsigned)hg < 32u && (unsigned)wg < 32u)
            v = *(const float4*)(x + ((((size_t)(b * 32 + hg) * 32 + wg) * CI
                                       + ci) * AI + a4 * 4));
        v.x = tf32r(v.x); v.y = tf32r(v.y); v.z = tf32r(v.z); v.w = tf32r(v.w);
        *(float4*)(patch + (size_t)r36 * 36 + a4 * 4) = v;
    }

    const int wm = wid >> 2, wn = wid & 3;       // warp M/N coords
    const int r = lid >> 2, q = lid & 3;

    // per-mt patch base (row36 of output pixel), constant across taps
    int rowbase[4]; int wcol[4];
    #pragma unroll
    for (int mt = 0; mt < 4; ++mt) {
        int m = wm * 64 + mt * 16 + r;           // m = hi2*32 + w
        rowbase[mt] = (m >> 5) * 36;
        wcol[mt]    = m & 31;
    }

    float acc[4][8][4];
    #pragma unroll
    for (int mt = 0; mt < 4; ++mt)
        #pragma unroll
        for (int nt = 0; nt < 8; ++nt)
            #pragma unroll
            for (int k = 0; k < 4; ++k) acc[mt][nt][k] = 0.f;

    #pragma unroll 1
    for (int t = 0; t < 25; ++t) {
        asm volatile("cp.async.wait_group 0;");
        __syncthreads();   // tap t visible; all warps done with buffer (t+1)&1

        if (t + 1 < 25) {  // prefetch next tap into the other buffer
            const float* src = g_Bf + (size_t)(t + 1) * (32 * 32 * 8);
            char* dst = bbuf + ((t + 1) & 1) * BBUF_BYTES;
            #pragma unroll
            for (int ii = 0; ii < 8; ++ii) {
                int i    = tid + ii * 256;
                int half = i & 1;
                int nl   = i >> 1;
                cp16(dst + (nl * 12 + half * 4) * 4, src + nl * 8 + half * 4);
            }
            asm volatile("cp.async.commit_group;");
        }

        const int dy = t / 5, dx = t % 5;
        const float* apt[4];
        #pragma unroll
        for (int mt = 0; mt < 4; ++mt)
            apt[mt] = patch + (size_t)(rowbase[mt] + dy * 36 + wcol[mt] + dx) * 36 + q;

        const char* bb = bbuf + (t & 1) * BBUF_BYTES;

        #pragma unroll
        for (int ksp = 0; ksp < 2; ++ksp) {
            uint4 bf[8];
            #pragma unroll
            for (int nt = 0; nt < 8; ++nt)
                bf[nt] = *(const uint4*)(bb +
                    (((wn * 8 + nt) * 32 + lid) * 12 + ksp * 4) * 4);

            #pragma unroll
            for (int ks2 = 0; ks2 < 2; ++ks2) {
                const int ko = (ksp * 2 + ks2) * 8;
                uint32_t A[4][4];
                #pragma unroll
                for (int mt = 0; mt < 4; ++mt) {
                    const float* p = apt[mt] + ko;
                    A[mt][0] = __float_as_uint(p[0]);
                    A[mt][1] = __float_as_uint(p[288]);   // row +8 (8*36)
                    A[mt][2] = __float_as_uint(p[4]);
                    A[mt][3] = __float_as_uint(p[292]);
                }
                #pragma unroll
                for (int mt = 0; mt < 4; ++mt)
                    #pragma unroll
                    for (int nt = 0; nt < 8; ++nt) {
                        uint32_t b0 = ks2 ? bf[nt].z : bf[nt].x;
                        uint32_t b1 = ks2 ? bf[nt].w : bf[nt].y;
                        MMA(acc[mt][nt], A[mt], b0, b1);
                    }
            }
        }
    }

    // ---- epilogue: store votes directly from accumulators ----
    #pragma unroll
    for (int mt = 0; mt < 4; ++mt) {
        int m   = wm * 64 + mt * 16 + r;
        int hi2 = m >> 5, w = m & 31;
        size_t base0 = (((size_t)(b * 32 + h0 + hi2)) * 32 + w) * 2048
                     + ci * 256 + wn * 64 + 2 * q;
        size_t base1 = base0 + 8 * 2048;         // row r+8 (same hi2)
        #pragma unroll
        for (int nt = 0; nt < 8; ++nt) {
            *(float2*)(g_votes + base0 + nt * 8) =
                make_float2(acc[mt][nt][0], acc[mt][nt][1]);
            *(float2*)(g_votes + base1 + nt * 8) =
                make_float2(acc[mt][nt][2], acc[mt][nt][3]);
        }
    }
}

// ---------------------------------------------------------------------------
// Routing kernel: votes in registers, logits/route in SMEM.
// Thread t = co*16 + ao; 16-lane shuffle reductions.
// ---------------------------------------------------------------------------
__global__ void __launch_bounds__(256)
routing_kernel(const float* __restrict__ bias, float* __restrict__ out) {
    __shared__ float lg[128];   // logits [ci][co]
    __shared__ float rt[128];   // route  [ci][co]

    const int t   = threadIdx.x;
    const int pix = blockIdx.x;
    const int co  = t >> 4, ao = t & 15;

    float v[8];
    const float* vp = g_votes + (size_t)pix * 2048 + t;
    #pragma unroll
    for (int c = 0; c < 8; ++c) v[c] = vp[c * 256];
    const float bv = __ldg(bias + t);
    if (t < 128) lg[t] = 0.f;
    __syncthreads();

    float a = 0.f;
    #pragma unroll 1
    for (int it = 0; it < 3; ++it) {
        if (t < 128) {   // (ci = t>>4, co' = t&15): softmax over co'
            float lv = lg[t];
            float m = lv;
            #pragma unroll
            for (int o = 8; o; o >>= 1)
                m = fmaxf(m, __shfl_xor_sync(0xffffffffu, m, o, 16));
            float e = expf(lv - m);
            float ssum = e;
            #pragma unroll
            for (int o = 8; o; o >>= 1)
                ssum += __shfl_xor_sync(0xffffffffu, ssum, o, 16);
            rt[t] = e / ssum;
        }
        __syncthreads();

        float p = bv;
        #pragma unroll
        for (int c = 0; c < 8; ++c) p += rt[c * 16 + co] * v[c];

        float ns = p * p;
        #pragma unroll
        for (int o = 8; o; o >>= 1)
            ns += __shfl_xor_sync(0xffffffffu, ns, o, 16);
        a = p * (sqrtf(ns) / (1.0f + ns));

        if (it < 2) {
            float sc[8];
            #pragma unroll
            for (int c = 0; c < 8; ++c) sc[c] = v[c] * a;
            #pragma unroll
            for (int o = 8; o; o >>= 1)
                #pragma unroll
                for (int c = 0; c < 8; ++c)
                    sc[c] += __shfl_xor_sync(0xffffffffu, sc[c], o, 16);
            if (ao == 0) {
                #pragma unroll
                for (int c = 0; c < 8; ++c) lg[c * 16 + co] += sc[c];
            }
            __syncthreads();
        }
    }
    out[(size_t)pix * 256 + t] = a;
}

// ---------------------------------------------------------------------------
extern "C" void kernel_launch(void* const* d_in, const int* in_sizes, int n_in,
                              void* d_out, int out_size) {
    const float* x  = (const float*)d_in[0];   // [16,32,32,8,32]
    const float* Wg = (const float*)d_in[1];   // [5,5,32,256]
    const float* bb = (const float*)d_in[2];   // [1,1,16,16]
    float* out = (float*)d_out;                // [16,32,32,16,16]

    cudaFuncSetAttribute(conv_kernel,
                         cudaFuncAttributeMaxDynamicSharedMemorySize, SMEM_BYTES);

    bfrag_kernel<<<dim3(25, 32), 256>>>(Wg);
    conv_kernel<<<dim3(8, CI, B_), 256, SMEM_BYTES>>>(x);
    routing_kernel<<<B_ * H_ * Wd_, 256>>>(bb, out);
}

// round 14
// speedup vs baseline: 7.9794x; 1.8584x over previous
#include <cuda_runtime.h>
#include <cuda_fp16.h>
#include <math.h>
#include <stdint.h>

#define B_   16
#define H_   32
#define Wd_  32
#define CI   8
#define AI   32
#define CO   16
#define AO   16
#define COAO 256

// votes scratch [pix][ci][co*ao] = 33.5M floats = 128 MiB
__device__ float g_votes[(size_t)B_ * H_ * Wd_ * CI * COAO];
// fp16 fragment-order weights: [tap 25][kstep 2][nt 32][lane 32][4 halves]
//   half(tap,ks,nt,l(r,q),j,h) = W[(tap*32 + ks*16 + 2q + 8j + h)*256 + nt*8 + r]
__device__ __half g_Bh[25 * 2 * 32 * 32 * 4];   // 400 KB

// ---- SMEM layout (bytes) --------------------------------------------------
// patch: 288 entries (8 halo rows x 36 cols) x 40 halves (32 atoms + 8 pad)
//   entry stride 40 halves = 20 words -> A-frag banks (20r + q) mod 32 distinct
#define PATCH_BYTES (288 * 40 * 2)      // 23040
#define BBUF_BYTES  16384               // one tap of fp16 B fragments
#define NBUF        3
#define SMEM_BYTES  (PATCH_BYTES + NBUF * BBUF_BYTES)   // 72192

__device__ __forceinline__ void cp16(void* dst, const void* src) {
    unsigned d = (unsigned)__cvta_generic_to_shared(dst);
    asm volatile("cp.async.cg.shared.global [%0], [%1], 16;" :: "r"(d), "l"(src));
}
__device__ __forceinline__ uint32_t h2u(__half2 h) {
    uint32_t u;
    asm("mov.b32 %0, %1;" : "=r"(u) : "r"(*(uint32_t*)&h));
    return u;
}

#define MMA16(d, A, b0, b1) \
    asm volatile( \
        "mma.sync.aligned.m16n8k16.row.col.f32.f16.f16.f32 " \
        "{%0,%1,%2,%3}, {%4,%5,%6,%7}, {%8,%9}, {%0,%1,%2,%3};" \
        : "+f"((d)[0]), "+f"((d)[1]), "+f"((d)[2]), "+f"((d)[3]) \
        : "r"((A)[0]), "r"((A)[1]), "r"((A)[2]), "r"((A)[3]), \
          "r"(b0), "r"(b1))

// ---------------------------------------------------------------------------
// Precompute fp16 fragment-order weights.
// ---------------------------------------------------------------------------
__global__ void __launch_bounds__(256)
bfrag_kernel(const float* __restrict__ W) {
    const int tap = blockIdx.x;          // 0..24
    const int nt  = blockIdx.y;          // 0..31
    const int t   = threadIdx.x;
    const int ks   = t >> 7;             // kstep 0..1
    const int rem  = t & 127;
    const int lane = rem >> 2;           // 0..31
    const int h4   = rem & 3;            // half slot within lane
    const int q = lane & 3, r = lane >> 2;
    const int j = h4 >> 1, h = h4 & 1;
    const int k = ks * 16 + 2 * q + 8 * j + h;
    const int n = nt * 8 + r;
    g_Bh[(((tap * 2 + ks) * 32 + nt) * 32 + lane) * 4 + h4] =
        __float2half_rn(W[(tap * 32 + k) * COAO + n]);
}

// ---------------------------------------------------------------------------
// Conv kernel: fp16 m16n8k16 mma.sync GEMM (fp32 accum).
// CTA = (hq, ci, b): M = 4h x 32w = 128, N = 256. 8 warps 2(M) x 4(N),
// warp tile 64x64. K = 25 taps x 32 atoms, 2 k16-steps per tap.
// B triple-buffered via cp.async (2 taps in flight).
// ---------------------------------------------------------------------------
__global__ void __launch_bounds__(256, 1)
conv_kernel(const float* __restrict__ x) {
    extern __shared__ char smem[];
    uint32_t*   patch_w = (uint32_t*)smem;            // patch as words (half2)
    char*       bbuf    = smem + PATCH_BYTES;

    const int tid = threadIdx.x;
    const int wid = tid >> 5, lid = tid & 31;
    const int hq = blockIdx.x, ci = blockIdx.y, b = blockIdx.z;
    const int h0 = hq * 4;

    // ---- prefetch B taps 0 and 1 ----
    #pragma unroll
    for (int tp = 0; tp < 2; ++tp) {
        const __half* src = g_Bh + (size_t)tp * 8192;
        char* dst = bbuf + tp * BBUF_BYTES;
        #pragma unroll
        for (int ii = 0; ii < 4; ++ii) {
            int i = tid + ii * 256;                   // 16B chunks, 0..1023
            cp16(dst + i * 16, src + i * 8);
        }
        asm volatile("cp.async.commit_group;");
    }

    // ---- load halo patch (fp16): rows h0-2..h0+5, cols -2..33, 32 atoms ----
    #pragma unroll
    for (int ii = 0; ii < 9; ++ii) {
        int i   = tid + ii * 256;                     // 0..2303
        int a4  = i & 7;                              // atom group (4 atoms)
        int e   = i >> 3;                             // entry = hi*36 + ww
        int ww  = e % 36;
        int hi  = e / 36;
        int hg  = h0 + hi - 2, wg = ww - 2;
        float4 v = make_float4(0.f, 0.f, 0.f, 0.f);
        if ((unsigned)hg < 32u && (unsigned)wg < 32u)
            v = *(const float4*)(x + ((((size_t)(b * 32 + hg) * 32 + wg) * CI
                                       + ci) * AI + a4 * 4));
        uint2 hv;
        hv.x = h2u(__floats2half2_rn(v.x, v.y));
        hv.y = h2u(__floats2half2_rn(v.z, v.w));
        *(uint2*)((char*)smem + e * 80 + a4 * 8) = hv;
    }

    const int wm = wid >> 2, wn = wid & 3;            // warp M/N coords
    const int r = lid >> 2, q = lid & 3;

    // per-mt constants: entry base (excluding dy/dx)
    int ebase[4];
    #pragma unroll
    for (int mt = 0; mt < 4; ++mt) {
        int m0   = wm * 64 + mt * 16;                 // m = hi2*32 + w, w = wb + r
        int hi2  = m0 >> 5;
        int wb   = m0 & 31;
        ebase[mt] = hi2 * 36 + wb + r;                // + dy*36 + dx per tap
    }

    float acc[4][8][4];
    #pragma unroll
    for (int mt = 0; mt < 4; ++mt)
        #pragma unroll
        for (int nt = 0; nt < 8; ++nt)
            #pragma unroll
            for (int k = 0; k < 4; ++k) acc[mt][nt][k] = 0.f;

    #pragma unroll 1
    for (int t = 0; t < 25; ++t) {
        if (t >= 23) asm volatile("cp.async.wait_group 0;");
        else         asm volatile("cp.async.wait_group 1;");
        __syncthreads();   // tap t visible; all warps done with buffer (t+2)%3

        if (t + 2 < 25) {  // prefetch tap t+2
            const __half* src = g_Bh + (size_t)(t + 2) * 8192;
            char* dst = bbuf + ((t + 2) % NBUF) * BBUF_BYTES;
            #pragma unroll
            for (int ii = 0; ii < 4; ++ii) {
                int i = tid + ii * 256;
                cp16(dst + i * 16, src + i * 8);
            }
            asm volatile("cp.async.commit_group;");
        }

        const int dy = t / 5, dx = t % 5;
        const int eoff = dy * 36 + dx;
        const char* bb = bbuf + (t % NBUF) * BBUF_BYTES;

        #pragma unroll
        for (int ks = 0; ks < 2; ++ks) {
            // B fragments: one LDS.64 per nt (conflict-free, contiguous lanes)
            uint2 bf[8];
            #pragma unroll
            for (int nt = 0; nt < 8; ++nt)
                bf[nt] = *(const uint2*)(bb +
                    (((ks * 32 + wn * 8 + nt) * 32 + lid) << 3));

            // A fragments: 4 LDS.32 per mt (banks (20r+q)%32, conflict-free)
            uint32_t A[4][4];
            #pragma unroll
            for (int mt = 0; mt < 4; ++mt) {
                const uint32_t* p = patch_w + (ebase[mt] + eoff) * 20
                                  + ks * 8 + q;
                A[mt][0] = p[0];
                A[mt][1] = p[160];     // row r+8 (entry +8 -> +160 words)
                A[mt][2] = p[4];       // k +8
                A[mt][3] = p[164];
            }

            #pragma unroll
            for (int mt = 0; mt < 4; ++mt)
                #pragma unroll
                for (int nt = 0; nt < 8; ++nt)
                    MMA16(acc[mt][nt], A[mt], bf[nt].x, bf[nt].y);
        }
    }

    // ---- epilogue: store votes directly from accumulators ----
    #pragma unroll
    for (int mt = 0; mt < 4; ++mt) {
        int m   = wm * 64 + mt * 16 + r;
        int hi2 = m >> 5, w = m & 31;
        size_t base0 = (((size_t)(b * 32 + h0 + hi2)) * 32 + w) * 2048
                     + ci * 256 + wn * 64 + 2 * q;
        size_t base1 = base0 + 8 * 2048;              // rows r+8 (w+8, same hi2)
        #pragma unroll
        for (int nt = 0; nt < 8; ++nt) {
            *(float2*)(g_votes + base0 + nt * 8) =
                make_float2(acc[mt][nt][0], acc[mt][nt][1]);
            *(float2*)(g_votes + base1 + nt * 8) =
                make_float2(acc[mt][nt][2], acc[mt][nt][3]);
        }
    }
}

// ---------------------------------------------------------------------------
// Routing kernel: votes in registers, logits/route in SMEM.
// Thread t = co*16 + ao; 16-lane shuffle reductions.
// ---------------------------------------------------------------------------
__global__ void __launch_bounds__(256)
routing_kernel(const float* __restrict__ bias, float* __restrict__ out) {
    __shared__ float lg[128];   // logits [ci][co]
    __shared__ float rt[128];   // route  [ci][co]

    const int t   = threadIdx.x;
    const int pix = blockIdx.x;
    const int co  = t >> 4, ao = t & 15;

    float v[8];
    const float* vp = g_votes + (size_t)pix * 2048 + t;
    #pragma unroll
    for (int c = 0; c < 8; ++c) v[c] = vp[c * 256];
    const float bv = __ldg(bias + t);
    if (t < 128) lg[t] = 0.f;
    __syncthreads();

    float a = 0.f;
    #pragma unroll 1
    for (int it = 0; it < 3; ++it) {
        if (t < 128) {   // (ci = t>>4, co' = t&15): softmax over co'
            float lv = lg[t];
            float m = lv;
            #pragma unroll
            for (int o = 8; o; o >>= 1)
                m = fmaxf(m, __shfl_xor_sync(0xffffffffu, m, o, 16));
            float e = expf(lv - m);
            float ssum = e;
            #pragma unroll
            for (int o = 8; o; o >>= 1)
                ssum += __shfl_xor_sync(0xffffffffu, ssum, o, 16);
            rt[t] = e / ssum;
        }
        __syncthreads();

        float p = bv;
        #pragma unroll
        for (int c = 0; c < 8; ++c) p += rt[c * 16 + co] * v[c];

        float ns = p * p;
        #pragma unroll
        for (int o = 8; o; o >>= 1)
            ns += __shfl_xor_sync(0xffffffffu, ns, o, 16);
        a = p * (sqrtf(ns) / (1.0f + ns));

        if (it < 2) {
            float sc[8];
            #pragma unroll
            for (int c = 0; c < 8; ++c) sc[c] = v[c] * a;
            #pragma unroll
            for (int o = 8; o; o >>= 1)
                #pragma unroll
                for (int c = 0; c < 8; ++c)
                    sc[c] += __shfl_xor_sync(0xffffffffu, sc[c], o, 16);
            if (ao == 0) {
                #pragma unroll
                for (int c = 0; c < 8; ++c) lg[c * 16 + co] += sc[c];
            }
            __syncthreads();
        }
    }
    out[(size_t)pix * 256 + t] = a;
}

// ---------------------------------------------------------------------------
extern "C" void kernel_launch(void* const* d_in, const int* in_sizes, int n_in,
                              void* d_out, int out_size) {
    const float* x  = (const float*)d_in[0];   // [16,32,32,8,32]
    const float* Wg = (const float*)d_in[1];   // [5,5,32,256]
    const float* bb = (const float*)d_in[2];   // [1,1,16,16]
    float* out = (float*)d_out;                // [16,32,32,16,16]

    cudaFuncSetAttribute(conv_kernel,
                         cudaFuncAttributeMaxDynamicSharedMemorySize, SMEM_BYTES);

    bfrag_kernel<<<dim3(25, 32), 256>>>(Wg);
    conv_kernel<<<dim3(8, CI, B_), 256, SMEM_BYTES>>>(x);
    routing_kernel<<<B_ * H_ * Wd_, 256>>>(bb, out);
}

// round 15
// speedup vs baseline: 10.1635x; 1.2737x over previous
#include <cuda_runtime.h>
#include <cuda_fp16.h>
#include <math.h>
#include <stdint.h>

#define B_   16
#define H_   32
#define Wd_  32
#define CI   8
#define AI   32
#define CO   16
#define AO   16
#define COAO 256

// votes scratch (fp16) [pix][ci][co*ao] = 33.5M halves = 64 MiB
__device__ __half g_vh[(size_t)B_ * H_ * Wd_ * CI * COAO];
// fp16 fragment-order weights: [tap 25][kstep 2][nt 32][lane 32][4 halves]
__device__ __half g_Bh[25 * 2 * 32 * 32 * 4];   // 400 KB

// ---- SMEM layout (bytes) --------------------------------------------------
// patch: 288 entries (8 halo rows x 36 cols) x 40 halves (32 atoms + 8 pad)
//   entry stride 40 halves = 20 words -> A-frag banks (20r + q) mod 32 distinct
#define PATCH_BYTES (288 * 40 * 2)      // 23040
#define BBUF_BYTES  16384               // one tap of fp16 B fragments
#define NBUF        3
#define SMEM_BYTES  (PATCH_BYTES + NBUF * BBUF_BYTES)   // 72192

__device__ __forceinline__ void cp16(void* dst, const void* src) {
    unsigned d = (unsigned)__cvta_generic_to_shared(dst);
    asm volatile("cp.async.cg.shared.global [%0], [%1], 16;" :: "r"(d), "l"(src));
}
__device__ __forceinline__ uint32_t h2u(__half2 h) {
    return *(uint32_t*)&h;
}

#define MMA16(d, A, b0, b1) \
    asm volatile( \
        "mma.sync.aligned.m16n8k16.row.col.f32.f16.f16.f32 " \
        "{%0,%1,%2,%3}, {%4,%5,%6,%7}, {%8,%9}, {%0,%1,%2,%3};" \
        : "+f"((d)[0]), "+f"((d)[1]), "+f"((d)[2]), "+f"((d)[3]) \
        : "r"((A)[0]), "r"((A)[1]), "r"((A)[2]), "r"((A)[3]), \
          "r"(b0), "r"(b1))

// ---------------------------------------------------------------------------
// Precompute fp16 fragment-order weights.
// ---------------------------------------------------------------------------
__global__ void __launch_bounds__(256)
bfrag_kernel(const float* __restrict__ W) {
    const int tap = blockIdx.x;          // 0..24
    const int nt  = blockIdx.y;          // 0..31
    const int t   = threadIdx.x;
    const int ks   = t >> 7;             // kstep 0..1
    const int rem  = t & 127;
    const int lane = rem >> 2;           // 0..31
    const int h4   = rem & 3;            // half slot within lane
    const int q = lane & 3, r = lane >> 2;
    const int j = h4 >> 1, h = h4 & 1;
    const int k = ks * 16 + 2 * q + 8 * j + h;
    const int n = nt * 8 + r;
    g_Bh[(((tap * 2 + ks) * 32 + nt) * 32 + lane) * 4 + h4] =
        __float2half_rn(W[(tap * 32 + k) * COAO + n]);
}

// ---------------------------------------------------------------------------
// Conv kernel: fp16 m16n8k16 mma.sync GEMM (fp32 accum), fp16 votes out.
// CTA = (hq, ci, b): M = 4h x 32w = 128, N = 256. 8 warps 2(M) x 4(N),
// warp tile 64x64. K = 25 taps x 32 atoms, 2 k16-steps per tap.
// ---------------------------------------------------------------------------
__global__ void __launch_bounds__(256, 1)
conv_kernel(const float* __restrict__ x) {
    extern __shared__ char smem[];
    uint32_t*   patch_w = (uint32_t*)smem;            // patch as words (half2)
    char*       bbuf    = smem + PATCH_BYTES;

    const int tid = threadIdx.x;
    const int wid = tid >> 5, lid = tid & 31;
    const int hq = blockIdx.x, ci = blockIdx.y, b = blockIdx.z;
    const int h0 = hq * 4;

    // ---- prefetch B taps 0 and 1 ----
    #pragma unroll
    for (int tp = 0; tp < 2; ++tp) {
        const __half* src = g_Bh + (size_t)tp * 8192;
        char* dst = bbuf + tp * BBUF_BYTES;
        #pragma unroll
        for (int ii = 0; ii < 4; ++ii) {
            int i = tid + ii * 256;
            cp16(dst + i * 16, src + i * 8);
        }
        asm volatile("cp.async.commit_group;");
    }

    // ---- load halo patch (fp16): rows h0-2..h0+5, cols -2..33, 32 atoms ----
    #pragma unroll
    for (int ii = 0; ii < 9; ++ii) {
        int i   = tid + ii * 256;                     // 0..2303
        int a4  = i & 7;                              // atom group (4 atoms)
        int e   = i >> 3;                             // entry = hi*36 + ww
        int ww  = e % 36;
        int hi  = e / 36;
        int hg  = h0 + hi - 2, wg = ww - 2;
        float4 v = make_float4(0.f, 0.f, 0.f, 0.f);
        if ((unsigned)hg < 32u && (unsigned)wg < 32u)
            v = *(const float4*)(x + ((((size_t)(b * 32 + hg) * 32 + wg) * CI
                                       + ci) * AI + a4 * 4));
        uint2 hv;
        hv.x = h2u(__floats2half2_rn(v.x, v.y));
        hv.y = h2u(__floats2half2_rn(v.z, v.w));
        *(uint2*)((char*)smem + e * 80 + a4 * 8) = hv;
    }

    const int wm = wid >> 2, wn = wid & 3;            // warp M/N coords
    const int r = lid >> 2, q = lid & 3;

    int ebase[4];
    #pragma unroll
    for (int mt = 0; mt < 4; ++mt) {
        int m0   = wm * 64 + mt * 16;                 // m = hi2*32 + w
        ebase[mt] = (m0 >> 5) * 36 + (m0 & 31) + r;
    }

    float acc[4][8][4];
    #pragma unroll
    for (int mt = 0; mt < 4; ++mt)
        #pragma unroll
        for (int nt = 0; nt < 8; ++nt)
            #pragma unroll
            for (int k = 0; k < 4; ++k) acc[mt][nt][k] = 0.f;

    #pragma unroll 1
    for (int t = 0; t < 25; ++t) {
        if (t >= 23) asm volatile("cp.async.wait_group 0;");
        else         asm volatile("cp.async.wait_group 1;");
        __syncthreads();

        if (t + 2 < 25) {
            const __half* src = g_Bh + (size_t)(t + 2) * 8192;
            char* dst = bbuf + ((t + 2) % NBUF) * BBUF_BYTES;
            #pragma unroll
            for (int ii = 0; ii < 4; ++ii) {
                int i = tid + ii * 256;
                cp16(dst + i * 16, src + i * 8);
            }
            asm volatile("cp.async.commit_group;");
        }

        const int dy = t / 5, dx = t % 5;
        const int eoff = dy * 36 + dx;
        const char* bb = bbuf + (t % NBUF) * BBUF_BYTES;

        #pragma unroll
        for (int ks = 0; ks < 2; ++ks) {
            uint2 bf[8];
            #pragma unroll
            for (int nt = 0; nt < 8; ++nt)
                bf[nt] = *(const uint2*)(bb +
                    (((ks * 32 + wn * 8 + nt) * 32 + lid) << 3));

            uint32_t A[4][4];
            #pragma unroll
            for (int mt = 0; mt < 4; ++mt) {
                const uint32_t* p = patch_w + (ebase[mt] + eoff) * 20
                                  + ks * 8 + q;
                A[mt][0] = p[0];
                A[mt][1] = p[160];     // row r+8 (entry +8 -> +160 words)
                A[mt][2] = p[4];       // k +8
                A[mt][3] = p[164];
            }

            #pragma unroll
            for (int mt = 0; mt < 4; ++mt)
                #pragma unroll
                for (int nt = 0; nt < 8; ++nt)
                    MMA16(acc[mt][nt], A[mt], bf[nt].x, bf[nt].y);
        }
    }

    // ---- epilogue: votes as fp16 (half2 packs from accumulator pairs) ----
    #pragma unroll
    for (int mt = 0; mt < 4; ++mt) {
        int m   = wm * 64 + mt * 16 + r;
        int hi2 = m >> 5, w = m & 31;
        size_t base0 = (((size_t)(b * 32 + h0 + hi2)) * 32 + w) * 2048
                     + ci * 256 + wn * 64 + 2 * q;          // half index
        size_t base1 = base0 + 8 * 2048;
        #pragma unroll
        for (int nt = 0; nt < 8; ++nt) {
            *(__half2*)(g_vh + base0 + nt * 8) =
                __floats2half2_rn(acc[mt][nt][0], acc[mt][nt][1]);
            *(__half2*)(g_vh + base1 + nt * 8) =
                __floats2half2_rn(acc[mt][nt][2], acc[mt][nt][3]);
        }
    }
}

// ---------------------------------------------------------------------------
// Routing kernel v3: 4 pixels/CTA, fp16 votes, vectorized over ao-quads.
// thread t: pixL = t>>6, j = t&63, co = j>>2, aq = j&3 (ao = aq*4..aq*4+3).
// ---------------------------------------------------------------------------
__global__ void __launch_bounds__(256)
routing_kernel(const float* __restrict__ bias, float* __restrict__ out) {
    __shared__ float lg[512];   // [pixL 4][ci 8][co 16]
    __shared__ float rt[512];

    const int t = threadIdx.x;
    const int pixL = t >> 6, j = t & 63;
    const int co = j >> 2;
    const size_t pix = (size_t)blockIdx.x * 4 + pixL;

    // votes: 8 coalesced 8B loads (4 halves each)
    float v[8][4];
    const __half* vp = g_vh + pix * 2048 + j * 4;   // co*16 + aq*4 == j*4
    #pragma unroll
    for (int c = 0; c < 8; ++c) {
        uint2 u = *(const uint2*)(vp + c * 256);
        float2 f0 = __half22float2(*(__half2*)&u.x);
        float2 f1 = __half22float2(*(__half2*)&u.y);
        v[c][0] = f0.x; v[c][1] = f0.y; v[c][2] = f1.x; v[c][3] = f1.y;
    }
    const float4 bb = ((const float4*)bias)[j];
    lg[t] = 0.f; lg[t + 256] = 0.f;
    __syncthreads();

    float a0 = 0.f, a1 = 0.f, a2 = 0.f, a3 = 0.f;
    #pragma unroll 1
    for (int it = 0; it < 3; ++it) {
        // softmax over co: entries t and t+256 (co = t&15 -> width-16 shuffles)
        {
            float l0 = lg[t], l1 = lg[t + 256];
            float m0 = l0, m1 = l1;
            #pragma unroll
            for (int o = 8; o; o >>= 1) {
                m0 = fmaxf(m0, __shfl_xor_sync(0xffffffffu, m0, o, 16));
                m1 = fmaxf(m1, __shfl_xor_sync(0xffffffffu, m1, o, 16));
            }
            float e0 = __expf(l0 - m0), e1 = __expf(l1 - m1);
            float s0 = e0, s1 = e1;
            #pragma unroll
            for (int o = 8; o; o >>= 1) {
                s0 += __shfl_xor_sync(0xffffffffu, s0, o, 16);
                s1 += __shfl_xor_sync(0xffffffffu, s1, o, 16);
            }
            rt[t] = e0 / s0; rt[t + 256] = e1 / s1;
        }
        __syncthreads();

        float p0 = bb.x, p1 = bb.y, p2 = bb.z, p3 = bb.w;
        #pragma unroll
        for (int c = 0; c < 8; ++c) {
            float rv = rt[pixL * 128 + c * 16 + co];
            p0 += rv * v[c][0]; p1 += rv * v[c][1];
            p2 += rv * v[c][2]; p3 += rv * v[c][3];
        }

        // squash: norm over 16 ao = 4 in-thread + width-4 butterfly (aq = lane&3)
        float ns = p0 * p0 + p1 * p1 + p2 * p2 + p3 * p3;
        ns += __shfl_xor_sync(0xffffffffu, ns, 1);
        ns += __shfl_xor_sync(0xffffffffu, ns, 2);
        float sq = sqrtf(ns) / (1.0f + ns);
        a0 = p0 * sq; a1 = p1 * sq; a2 = p2 * sq; a3 = p3 * sq;

        if (it < 2) {
            #pragma unroll
            for (int c = 0; c < 8; ++c) {
                float sc = v[c][0] * a0 + v[c][1] * a1
                         + v[c][2] * a2 + v[c][3] * a3;
                sc += __shfl_xor_sync(0xffffffffu, sc, 1);
                sc += __shfl_xor_sync(0xffffffffu, sc, 2);
                if ((j & 3) == 0) lg[pixL * 128 + c * 16 + co] += sc;
            }
            __syncthreads();
        }
    }
    ((float4*)out)[pix * 64 + j] = make_float4(a0, a1, a2, a3);
}

// ---------------------------------------------------------------------------
extern "C" void kernel_launch(void* const* d_in, const int* in_sizes, int n_in,
                              void* d_out, int out_size) {
    const float* x  = (const float*)d_in[0];   // [16,32,32,8,32]
    const float* Wg = (const float*)d_in[1];   // [5,5,32,256]
    const float* bb = (const float*)d_in[2];   // [1,1,16,16]
    float* out = (float*)d_out;                // [16,32,32,16,16]

    cudaFuncSetAttribute(conv_kernel,
                         cudaFuncAttributeMaxDynamicSharedMemorySize, SMEM_BYTES);

    bfrag_kernel<<<dim3(25, 32), 256>>>(Wg);
    conv_kernel<<<dim3(8, CI, B_), 256, SMEM_BYTES>>>(x);
    routing_kernel<<<B_ * H_ * Wd_ / 4, 256>>>(bb, out);
}